// round 2
// baseline (speedup 1.0000x reference)
#include <cuda_runtime.h>
#include <cuda_bf16.h>
#include <cstdint>

#define T_TOK 8192
#define D_DIM 768
#define H_DIM 3072
#define E_NUM 8
#define NA    16384   // T_TOK * 2 assignments

// ---------------- scratch (device globals; no runtime allocation) ----------------
__device__ float g_partial_mean[1024 * E_NUM];
__device__ int   g_topk_id[NA];
__device__ float g_topk_gate[NA];
__device__ int   g_counts[E_NUM];
__device__ int   g_offsets[E_NUM];
__device__ int   g_cursors[E_NUM];
__device__ int   g_rowtok[NA];       // global row -> token
__device__ int   g_inv[NA];          // assignment slot -> global row
__device__ float g_act[(size_t)NA * H_DIM];     // SwiGLU activations (201 MB)
__device__ float g_outbuf[(size_t)NA * D_DIM];  // per-assignment down-proj (48 MB)

// ---------------- packed fp32x2 helpers (Blackwell FFMA2 path) ----------------
#define FMA2(c, a, b) asm("fma.rn.f32x2 %0, %1, %2, %0;" : "+l"(c) : "l"(a), "l"(b))

__device__ __forceinline__ unsigned long long pack2(float v) {
    unsigned long long p;
    unsigned int u = __float_as_uint(v);
    asm("mov.b64 %0, {%1, %1};" : "=l"(p) : "r"(u));
    return p;
}
__device__ __forceinline__ void unpack2(unsigned long long p, float& lo, float& hi) {
    unsigned int a, b;
    asm("mov.b64 {%0, %1}, %2;" : "=r"(a), "=r"(b) : "l"(p));
    lo = __uint_as_float(a);
    hi = __uint_as_float(b);
}

// ---------------- 1) gating: logits, softmax mean (LB loss partials), top-2 gates ----------------
__global__ __launch_bounds__(256) void gate_kernel(
    const float* __restrict__ x, const float* __restrict__ gw,
    const float* __restrict__ nw, const float* __restrict__ noise)
{
    __shared__ float sgw[E_NUM][D_DIM];   // 24 KB
    __shared__ float swm[8][E_NUM];
    int tid = threadIdx.x;
    for (int i = tid; i < E_NUM * D_DIM; i += 256) sgw[i / D_DIM][i % D_DIM] = gw[i];
    __syncthreads();

    int warp = tid >> 5, lane = tid & 31;
    int t = blockIdx.x * 8 + warp;

    float acc[E_NUM];
#pragma unroll
    for (int e = 0; e < E_NUM; e++) acc[e] = 0.f;
    const float* xr = x + (size_t)t * D_DIM;
    for (int d = lane; d < D_DIM; d += 32) {
        float xv = xr[d];
#pragma unroll
        for (int e = 0; e < E_NUM; e++) acc[e] += xv * sgw[e][d];
    }
#pragma unroll
    for (int e = 0; e < E_NUM; e++) {
#pragma unroll
        for (int o = 16; o > 0; o >>= 1) acc[e] += __shfl_xor_sync(0xffffffffu, acc[e], o);
    }

    if (lane == 0) {
        // clean softmax -> per-warp contribution to gate_weights mean
        float m = acc[0];
#pragma unroll
        for (int e = 1; e < E_NUM; e++) m = fmaxf(m, acc[e]);
        float p[E_NUM]; float s = 0.f;
#pragma unroll
        for (int e = 0; e < E_NUM; e++) { p[e] = expf(acc[e] - m); s += p[e]; }
        float invs = 1.f / s;
#pragma unroll
        for (int e = 0; e < E_NUM; e++) swm[warp][e] = p[e] * invs;

        // noisy logits (noise_weight is data; zeros at init -> exact no-op)
        float nv[E_NUM];
#pragma unroll
        for (int e = 0; e < E_NUM; e++) nv[e] = acc[e] + noise[(size_t)t * E_NUM + e] * nw[e];

        // top-2, ties -> lower index (matches jax top_k)
        int i0 = 0;
#pragma unroll
        for (int e = 1; e < E_NUM; e++) if (nv[e] > nv[i0]) i0 = e;
        int i1 = (i0 == 0) ? 1 : 0;
#pragma unroll
        for (int e = 0; e < E_NUM; e++) if (e != i0 && e != i1 && nv[e] > nv[i1]) i1 = e;

        float mm = fmaxf(nv[i0], nv[i1]);
        float q0 = expf(nv[i0] - mm), q1 = expf(nv[i1] - mm);
        float qi = 1.f / (q0 + q1);
        g_topk_id[2 * t]     = i0;  g_topk_gate[2 * t]     = q0 * qi;
        g_topk_id[2 * t + 1] = i1;  g_topk_gate[2 * t + 1] = q1 * qi;
    }
    __syncthreads();
    if (tid < E_NUM) {
        float s = 0.f;
#pragma unroll
        for (int w = 0; w < 8; w++) s += swm[w][tid];
        g_partial_mean[blockIdx.x * E_NUM + tid] = s;
    }
}

// ---------------- 2) reduce loss, compute expert counts/offsets, zero cursors ----------------
__global__ __launch_bounds__(256) void scan_loss_kernel(float* __restrict__ loss_out)
{
    __shared__ int   cred[E_NUM * 256];   // 8 KB
    __shared__ float red[256];
    int tid = threadIdx.x;

    int lc[E_NUM];
#pragma unroll
    for (int e = 0; e < E_NUM; e++) lc[e] = 0;
    for (int i = tid; i < NA; i += 256) {
        int id = g_topk_id[i];
#pragma unroll
        for (int e = 0; e < E_NUM; e++) lc[e] += (id == e);
    }
#pragma unroll
    for (int e = 0; e < E_NUM; e++) cred[e * 256 + tid] = lc[e];

    float lm = 0.f;
    int e8 = tid & 7;
    for (int b = tid >> 3; b < 1024; b += 32) lm += g_partial_mean[b * E_NUM + e8];
    red[tid] = lm;
    __syncthreads();

    if (tid < E_NUM) {
        int c = 0;
        for (int i = 0; i < 256; i++) c += cred[tid * 256 + i];
        g_counts[tid]  = c;
        g_cursors[tid] = 0;
        float s = 0.f;
        for (int i = tid; i < 256; i += 8) s += red[i];
        red[tid] = s;
    }
    __syncthreads();

    if (tid == 0) {
        int off = 0;
        float loss = 0.f;
        for (int e = 0; e < E_NUM; e++) {
            g_offsets[e] = off; off += g_counts[e];
            float m = red[e] * (1.f / 8192.f) - 0.125f;
            loss += m * m;
        }
        *loss_out = loss * (0.01f / 8.f);
    }
}

// ---------------- 3) build per-expert row lists ----------------
__global__ __launch_bounds__(256) void build_kernel()
{
    int i = blockIdx.x * 256 + threadIdx.x;
    if (i < NA) {
        int e = g_topk_id[i];
        int pos = atomicAdd(&g_cursors[e], 1);
        int r = g_offsets[e] + pos;
        g_rowtok[r] = i >> 1;
        g_inv[i] = r;
    }
}

// ---------------- 4) fused GEMM1: act = (x@w1+b1) * silu(x@w2+b2), gathered rows ----------------
// BM=128 BN=64 BK=16, 256 threads, per-thread 8x4 per matrix (m-paired f32x2 accum)
__global__ __launch_bounds__(256) void gemm1_kernel(
    const float* __restrict__ x,
    const float* __restrict__ w1, const float* __restrict__ b1,
    const float* __restrict__ w2, const float* __restrict__ b2)
{
    const int e = blockIdx.z;
    const int Me = g_counts[e];
    const int m0 = blockIdx.y * 128;
    if (m0 >= Me) return;
    const int n0 = blockIdx.x * 64;
    const int goff = g_offsets[e];
    const float* W1 = w1 + (size_t)e * D_DIM * H_DIM;
    const float* W2 = w2 + (size_t)e * D_DIM * H_DIM;

    __shared__ __align__(16) float As[16][132];
    __shared__ __align__(16) float Bs1[16][68];
    __shared__ __align__(16) float Bs2[16][68];

    const int tid  = threadIdx.x;
    const int arow = tid >> 1;
    const int akq  = (tid & 1) * 2;
    const float* xrow = nullptr;
    if (m0 + arow < Me) xrow = x + (size_t)g_rowtok[goff + m0 + arow] * D_DIM;

    const int bkr  = tid >> 4;
    const int bcol = (tid & 15) * 4;
    const float* pb1 = W1 + (size_t)bkr * H_DIM + n0 + bcol;
    const float* pb2 = W2 + (size_t)bkr * H_DIM + n0 + bcol;

    const int ty = tid >> 4;
    const int tx = tid & 15;

    unsigned long long acc1[4][4], acc2[4][4];
#pragma unroll
    for (int i = 0; i < 4; i++)
#pragma unroll
        for (int j = 0; j < 4; j++) { acc1[i][j] = 0ull; acc2[i][j] = 0ull; }

    for (int kk = 0; kk < D_DIM; kk += 16) {
#pragma unroll
        for (int q = 0; q < 2; q++) {
            int kq = akq + q;
            float4 v = xrow ? *(const float4*)(xrow + kk + kq * 4)
                            : make_float4(0.f, 0.f, 0.f, 0.f);
            As[kq * 4 + 0][arow] = v.x; As[kq * 4 + 1][arow] = v.y;
            As[kq * 4 + 2][arow] = v.z; As[kq * 4 + 3][arow] = v.w;
        }
        *(float4*)&Bs1[bkr][bcol] = *(const float4*)(pb1 + (size_t)kk * H_DIM);
        *(float4*)&Bs2[bkr][bcol] = *(const float4*)(pb2 + (size_t)kk * H_DIM);
        __syncthreads();

#pragma unroll
        for (int k = 0; k < 16; k++) {
            ulonglong2 aA = *(ulonglong2*)&As[k][ty * 8];
            ulonglong2 aB = *(ulonglong2*)&As[k][ty * 8 + 4];
            unsigned long long ap[4] = {aA.x, aA.y, aB.x, aB.y};
            float4 bv1 = *(float4*)&Bs1[k][tx * 4];
            float4 bv2 = *(float4*)&Bs2[k][tx * 4];
            unsigned long long bb1[4] = {pack2(bv1.x), pack2(bv1.y), pack2(bv1.z), pack2(bv1.w)};
            unsigned long long bb2[4] = {pack2(bv2.x), pack2(bv2.y), pack2(bv2.z), pack2(bv2.w)};
#pragma unroll
            for (int i = 0; i < 4; i++) {
#pragma unroll
                for (int j = 0; j < 4; j++) {
                    FMA2(acc1[i][j], ap[i], bb1[j]);
                    FMA2(acc2[i][j], ap[i], bb2[j]);
                }
            }
        }
        __syncthreads();
    }

    float bia1[4], bia2[4];
#pragma unroll
    for (int j = 0; j < 4; j++) {
        bia1[j] = b1[e * H_DIM + n0 + tx * 4 + j];
        bia2[j] = b2[e * H_DIM + n0 + tx * 4 + j];
    }
#pragma unroll
    for (int i = 0; i < 4; i++) {
        int rlo = m0 + ty * 8 + 2 * i;
        float olo[4], ohi[4];
#pragma unroll
        for (int j = 0; j < 4; j++) {
            float h1l, h1h, h2l, h2h;
            unpack2(acc1[i][j], h1l, h1h);
            unpack2(acc2[i][j], h2l, h2h);
            float z1l = h1l + bia1[j], z2l = h2l + bia2[j];
            float z1h = h1h + bia1[j], z2h = h2h + bia2[j];
            olo[j] = z1l * (z2l / (1.f + expf(-z2l)));
            ohi[j] = z1h * (z2h / (1.f + expf(-z2h)));
        }
        if (rlo < Me)
            *(float4*)&g_act[(size_t)(goff + rlo) * H_DIM + n0 + tx * 4] =
                make_float4(olo[0], olo[1], olo[2], olo[3]);
        if (rlo + 1 < Me)
            *(float4*)&g_act[(size_t)(goff + rlo + 1) * H_DIM + n0 + tx * 4] =
                make_float4(ohi[0], ohi[1], ohi[2], ohi[3]);
    }
}

// ---------------- 5) GEMM2: outbuf = act @ wp[e] ----------------
// BM=128 BN=128 BK=16, 256 threads, per-thread 8x8 (m-paired f32x2 accum)
__global__ __launch_bounds__(256) void gemm2_kernel(const float* __restrict__ wp)
{
    const int e = blockIdx.z;
    const int Me = g_counts[e];
    const int m0 = blockIdx.y * 128;
    if (m0 >= Me) return;
    const int n0 = blockIdx.x * 128;
    const int goff = g_offsets[e];
    const float* W = wp + (size_t)e * H_DIM * D_DIM;

    __shared__ __align__(16) float As[16][132];
    __shared__ __align__(16) float Bs[16][132];

    const int tid  = threadIdx.x;
    const int arow = tid >> 1;
    const int akq  = (tid & 1) * 2;
    const float* arp = nullptr;
    if (m0 + arow < Me) arp = g_act + (size_t)(goff + m0 + arow) * H_DIM;

    const int ty = tid >> 4, tx = tid & 15;
    unsigned long long acc[4][8];
#pragma unroll
    for (int i = 0; i < 4; i++)
#pragma unroll
        for (int j = 0; j < 8; j++) acc[i][j] = 0ull;

    for (int kk = 0; kk < H_DIM; kk += 16) {
#pragma unroll
        for (int q = 0; q < 2; q++) {
            int kq = akq + q;
            float4 v = arp ? *(const float4*)(arp + kk + kq * 4)
                           : make_float4(0.f, 0.f, 0.f, 0.f);
            As[kq * 4 + 0][arow] = v.x; As[kq * 4 + 1][arow] = v.y;
            As[kq * 4 + 2][arow] = v.z; As[kq * 4 + 3][arow] = v.w;
        }
#pragma unroll
        for (int q = 0; q < 2; q++) {
            int idx = tid * 2 + q;
            int kr = idx >> 5, c4 = idx & 31;
            *(float4*)&Bs[kr][c4 * 4] =
                *(const float4*)(W + (size_t)(kk + kr) * D_DIM + n0 + c4 * 4);
        }
        __syncthreads();

#pragma unroll
        for (int k = 0; k < 16; k++) {
            ulonglong2 aA = *(ulonglong2*)&As[k][ty * 8];
            ulonglong2 aB = *(ulonglong2*)&As[k][ty * 8 + 4];
            unsigned long long ap[4] = {aA.x, aA.y, aB.x, aB.y};
            float4 bv0 = *(float4*)&Bs[k][tx * 8];
            float4 bv1 = *(float4*)&Bs[k][tx * 8 + 4];
            unsigned long long bb[8] = {pack2(bv0.x), pack2(bv0.y), pack2(bv0.z), pack2(bv0.w),
                                        pack2(bv1.x), pack2(bv1.y), pack2(bv1.z), pack2(bv1.w)};
#pragma unroll
            for (int i = 0; i < 4; i++)
#pragma unroll
                for (int j = 0; j < 8; j++) FMA2(acc[i][j], ap[i], bb[j]);
        }
        __syncthreads();
    }

#pragma unroll
    for (int i = 0; i < 4; i++) {
        int rlo = m0 + ty * 8 + 2 * i;
        float olo[8], ohi[8];
#pragma unroll
        for (int j = 0; j < 8; j++) unpack2(acc[i][j], olo[j], ohi[j]);
        if (rlo < Me) {
            float* dst = &g_outbuf[(size_t)(goff + rlo) * D_DIM + n0 + tx * 8];
            *(float4*)dst       = make_float4(olo[0], olo[1], olo[2], olo[3]);
            *(float4*)(dst + 4) = make_float4(olo[4], olo[5], olo[6], olo[7]);
        }
        if (rlo + 1 < Me) {
            float* dst = &g_outbuf[(size_t)(goff + rlo + 1) * D_DIM + n0 + tx * 8];
            *(float4*)dst       = make_float4(ohi[0], ohi[1], ohi[2], ohi[3]);
            *(float4*)(dst + 4) = make_float4(ohi[4], ohi[5], ohi[6], ohi[7]);
        }
    }
}

// ---------------- 6) combine: y[t] = g0*(o0+bp[e0]) + g1*(o1+bp[e1]) ----------------
__global__ __launch_bounds__(256) void combine_kernel(const float* __restrict__ bp,
                                                      float* __restrict__ y)
{
    int idx = blockIdx.x * 256 + threadIdx.x;
    if (idx >= T_TOK * D_DIM) return;
    int t = idx / D_DIM, d = idx - t * D_DIM;
    int i0 = 2 * t, i1 = 2 * t + 1;
    int r0 = g_inv[i0], r1 = g_inv[i1];
    int e0 = g_topk_id[i0], e1 = g_topk_id[i1];
    float g0 = g_topk_gate[i0], g1 = g_topk_gate[i1];
    float v0 = g_outbuf[(size_t)r0 * D_DIM + d] + bp[e0 * D_DIM + d];
    float v1 = g_outbuf[(size_t)r1 * D_DIM + d] + bp[e1 * D_DIM + d];
    y[idx] = g0 * v0 + g1 * v1;
}

// ---------------- launch ----------------
extern "C" void kernel_launch(void* const* d_in, const int* in_sizes, int n_in,
                              void* d_out, int out_size)
{
    const float* x      = (const float*)d_in[0];
    const float* gate_w = (const float*)d_in[1];
    const float* nw     = (const float*)d_in[2];
    const float* noise  = (const float*)d_in[3];
    const float* w1     = (const float*)d_in[4];
    const float* b1     = (const float*)d_in[5];
    const float* w2     = (const float*)d_in[6];
    const float* b2     = (const float*)d_in[7];
    const float* wp     = (const float*)d_in[8];
    const float* bp     = (const float*)d_in[9];
    float* y = (float*)d_out;
    float* loss_ptr = y + (out_size - 1);

    gate_kernel<<<1024, 256>>>(x, gate_w, nw, noise);
    scan_loss_kernel<<<1, 256>>>(loss_ptr);
    build_kernel<<<64, 256>>>();
    gemm1_kernel<<<dim3(48, 128, 8), 256>>>(x, w1, b1, w2, b2);
    gemm2_kernel<<<dim3(6, 128, 8), 256>>>(wp);
    combine_kernel<<<24576, 256>>>(bp, y);
}

// round 3
// speedup vs baseline: 1.0019x; 1.0019x over previous
#include <cuda_runtime.h>
#include <cuda_bf16.h>
#include <cstdint>

#define T_TOK 8192
#define D_DIM 768
#define H_DIM 3072
#define E_NUM 8
#define NA    16384   // T_TOK * 2 assignments

// ---------------- scratch (device globals; no runtime allocation) ----------------
__device__ float g_partial_mean[1024 * E_NUM];
__device__ int   g_topk_id[NA];
__device__ float g_topk_gate[NA];
__device__ int   g_counts[E_NUM];
__device__ int   g_offsets[E_NUM];
__device__ int   g_cursors[E_NUM];
__device__ int   g_rowtok[NA];       // global row -> token
__device__ int   g_inv[NA];          // assignment slot -> global row
__device__ float g_act[(size_t)NA * H_DIM];     // SwiGLU activations (201 MB)
__device__ float g_outbuf[(size_t)NA * D_DIM];  // per-assignment down-proj (48 MB)

// ---------------- packed fp32x2 helpers (Blackwell FFMA2 path) ----------------
#define FMA2(c, a, b) asm("fma.rn.f32x2 %0, %1, %2, %0;" : "+l"(c) : "l"(a), "l"(b))

__device__ __forceinline__ unsigned long long pack2(float v) {
    unsigned long long p;
    unsigned int u = __float_as_uint(v);
    asm("mov.b64 %0, {%1, %1};" : "=l"(p) : "r"(u));
    return p;
}
__device__ __forceinline__ void unpack2(unsigned long long p, float& lo, float& hi) {
    unsigned int a, b;
    asm("mov.b64 {%0, %1}, %2;" : "=r"(a), "=r"(b) : "l"(p));
    lo = __uint_as_float(a);
    hi = __uint_as_float(b);
}

// ---------------- 1) gating: logits, softmax mean (LB loss partials), top-2 gates ----------------
__global__ __launch_bounds__(256) void gate_kernel(
    const float* __restrict__ x, const float* __restrict__ gw,
    const float* __restrict__ nw, const float* __restrict__ noise)
{
    __shared__ float sgw[E_NUM][D_DIM];   // 24 KB
    __shared__ float swm[8][E_NUM];
    int tid = threadIdx.x;
    for (int i = tid; i < E_NUM * D_DIM; i += 256) sgw[i / D_DIM][i % D_DIM] = gw[i];
    __syncthreads();

    int warp = tid >> 5, lane = tid & 31;
    int t = blockIdx.x * 8 + warp;

    float acc[E_NUM];
#pragma unroll
    for (int e = 0; e < E_NUM; e++) acc[e] = 0.f;
    const float* xr = x + (size_t)t * D_DIM;
    for (int d = lane; d < D_DIM; d += 32) {
        float xv = xr[d];
#pragma unroll
        for (int e = 0; e < E_NUM; e++) acc[e] += xv * sgw[e][d];
    }
#pragma unroll
    for (int e = 0; e < E_NUM; e++) {
#pragma unroll
        for (int o = 16; o > 0; o >>= 1) acc[e] += __shfl_xor_sync(0xffffffffu, acc[e], o);
    }

    if (lane == 0) {
        // clean softmax -> per-warp contribution to gate_weights mean
        float m = acc[0];
#pragma unroll
        for (int e = 1; e < E_NUM; e++) m = fmaxf(m, acc[e]);
        float p[E_NUM]; float s = 0.f;
#pragma unroll
        for (int e = 0; e < E_NUM; e++) { p[e] = expf(acc[e] - m); s += p[e]; }
        float invs = 1.f / s;
#pragma unroll
        for (int e = 0; e < E_NUM; e++) swm[warp][e] = p[e] * invs;

        // noisy logits (noise_weight is data; zeros at init -> exact no-op)
        float nv[E_NUM];
#pragma unroll
        for (int e = 0; e < E_NUM; e++) nv[e] = acc[e] + noise[(size_t)t * E_NUM + e] * nw[e];

        // top-2, ties -> lower index (matches jax top_k)
        int i0 = 0;
#pragma unroll
        for (int e = 1; e < E_NUM; e++) if (nv[e] > nv[i0]) i0 = e;
        int i1 = (i0 == 0) ? 1 : 0;
#pragma unroll
        for (int e = 0; e < E_NUM; e++) if (e != i0 && e != i1 && nv[e] > nv[i1]) i1 = e;

        float mm = fmaxf(nv[i0], nv[i1]);
        float q0 = expf(nv[i0] - mm), q1 = expf(nv[i1] - mm);
        float qi = 1.f / (q0 + q1);
        g_topk_id[2 * t]     = i0;  g_topk_gate[2 * t]     = q0 * qi;
        g_topk_id[2 * t + 1] = i1;  g_topk_gate[2 * t + 1] = q1 * qi;
    }
    __syncthreads();
    if (tid < E_NUM) {
        float s = 0.f;
#pragma unroll
        for (int w = 0; w < 8; w++) s += swm[w][tid];
        g_partial_mean[blockIdx.x * E_NUM + tid] = s;
    }
}

// ---------------- 2) reduce loss, compute expert counts/offsets, zero cursors ----------------
__global__ __launch_bounds__(256) void scan_loss_kernel(float* __restrict__ loss_out)
{
    __shared__ int   cred[E_NUM * 256];   // 8 KB
    __shared__ float red[256];
    int tid = threadIdx.x;

    int lc[E_NUM];
#pragma unroll
    for (int e = 0; e < E_NUM; e++) lc[e] = 0;
    for (int i = tid; i < NA; i += 256) {
        int id = g_topk_id[i];
#pragma unroll
        for (int e = 0; e < E_NUM; e++) lc[e] += (id == e);
    }
#pragma unroll
    for (int e = 0; e < E_NUM; e++) cred[e * 256 + tid] = lc[e];

    float lm = 0.f;
    int e8 = tid & 7;
    for (int b = tid >> 3; b < 1024; b += 32) lm += g_partial_mean[b * E_NUM + e8];
    red[tid] = lm;
    __syncthreads();

    if (tid < E_NUM) {
        int c = 0;
        for (int i = 0; i < 256; i++) c += cred[tid * 256 + i];
        g_counts[tid]  = c;
        g_cursors[tid] = 0;
        float s = 0.f;
        for (int i = tid; i < 256; i += 8) s += red[i];
        red[tid] = s;
    }
    __syncthreads();

    if (tid == 0) {
        int off = 0;
        float loss = 0.f;
        for (int e = 0; e < E_NUM; e++) {
            g_offsets[e] = off; off += g_counts[e];
            float m = red[e] * (1.f / 8192.f) - 0.125f;
            loss += m * m;
        }
        *loss_out = loss * (0.01f / 8.f);
    }
}

// ---------------- 3) build per-expert row lists ----------------
__global__ __launch_bounds__(256) void build_kernel()
{
    int i = blockIdx.x * 256 + threadIdx.x;
    if (i < NA) {
        int e = g_topk_id[i];
        int pos = atomicAdd(&g_cursors[e], 1);
        int r = g_offsets[e] + pos;
        g_rowtok[r] = i >> 1;
        g_inv[i] = r;
    }
}

// ---------------- 4) fused GEMM1: act = (x@w1+b1) * silu(x@w2+b2), gathered rows ----------------
// BM=128 BN=64 BK=16, 256 threads, per-thread 8x4 per matrix (m-paired f32x2 accum)
__global__ __launch_bounds__(256) void gemm1_kernel(
    const float* __restrict__ x,
    const float* __restrict__ w1, const float* __restrict__ b1,
    const float* __restrict__ w2, const float* __restrict__ b2)
{
    const int e = blockIdx.z;
    const int Me = g_counts[e];
    const int m0 = blockIdx.y * 128;
    if (m0 >= Me) return;
    const int n0 = blockIdx.x * 64;
    const int goff = g_offsets[e];
    const float* W1 = w1 + (size_t)e * D_DIM * H_DIM;
    const float* W2 = w2 + (size_t)e * D_DIM * H_DIM;

    __shared__ __align__(16) float As[16][132];
    __shared__ __align__(16) float Bs1[16][68];
    __shared__ __align__(16) float Bs2[16][68];

    const int tid  = threadIdx.x;
    const int arow = tid >> 1;
    const int akq  = (tid & 1) * 2;
    const float* xrow = nullptr;
    if (m0 + arow < Me) xrow = x + (size_t)g_rowtok[goff + m0 + arow] * D_DIM;

    const int bkr  = tid >> 4;
    const int bcol = (tid & 15) * 4;
    const float* pb1 = W1 + (size_t)bkr * H_DIM + n0 + bcol;
    const float* pb2 = W2 + (size_t)bkr * H_DIM + n0 + bcol;

    const int ty = tid >> 4;
    const int tx = tid & 15;

    unsigned long long acc1[4][4], acc2[4][4];
#pragma unroll
    for (int i = 0; i < 4; i++)
#pragma unroll
        for (int j = 0; j < 4; j++) { acc1[i][j] = 0ull; acc2[i][j] = 0ull; }

    for (int kk = 0; kk < D_DIM; kk += 16) {
#pragma unroll
        for (int q = 0; q < 2; q++) {
            int kq = akq + q;
            float4 v = xrow ? *(const float4*)(xrow + kk + kq * 4)
                            : make_float4(0.f, 0.f, 0.f, 0.f);
            As[kq * 4 + 0][arow] = v.x; As[kq * 4 + 1][arow] = v.y;
            As[kq * 4 + 2][arow] = v.z; As[kq * 4 + 3][arow] = v.w;
        }
        *(float4*)&Bs1[bkr][bcol] = *(const float4*)(pb1 + (size_t)kk * H_DIM);
        *(float4*)&Bs2[bkr][bcol] = *(const float4*)(pb2 + (size_t)kk * H_DIM);
        __syncthreads();

#pragma unroll
        for (int k = 0; k < 16; k++) {
            ulonglong2 aA = *(ulonglong2*)&As[k][ty * 8];
            ulonglong2 aB = *(ulonglong2*)&As[k][ty * 8 + 4];
            unsigned long long ap[4] = {aA.x, aA.y, aB.x, aB.y};
            float4 bv1 = *(float4*)&Bs1[k][tx * 4];
            float4 bv2 = *(float4*)&Bs2[k][tx * 4];
            unsigned long long bb1[4] = {pack2(bv1.x), pack2(bv1.y), pack2(bv1.z), pack2(bv1.w)};
            unsigned long long bb2[4] = {pack2(bv2.x), pack2(bv2.y), pack2(bv2.z), pack2(bv2.w)};
#pragma unroll
            for (int i = 0; i < 4; i++) {
#pragma unroll
                for (int j = 0; j < 4; j++) {
                    FMA2(acc1[i][j], ap[i], bb1[j]);
                    FMA2(acc2[i][j], ap[i], bb2[j]);
                }
            }
        }
        __syncthreads();
    }

    float bia1[4], bia2[4];
#pragma unroll
    for (int j = 0; j < 4; j++) {
        bia1[j] = b1[e * H_DIM + n0 + tx * 4 + j];
        bia2[j] = b2[e * H_DIM + n0 + tx * 4 + j];
    }
#pragma unroll
    for (int i = 0; i < 4; i++) {
        int rlo = m0 + ty * 8 + 2 * i;
        float olo[4], ohi[4];
#pragma unroll
        for (int j = 0; j < 4; j++) {
            float h1l, h1h, h2l, h2h;
            unpack2(acc1[i][j], h1l, h1h);
            unpack2(acc2[i][j], h2l, h2h);
            float z1l = h1l + bia1[j], z2l = h2l + bia2[j];
            float z1h = h1h + bia1[j], z2h = h2h + bia2[j];
            olo[j] = z1l * (z2l / (1.f + expf(-z2l)));
            ohi[j] = z1h * (z2h / (1.f + expf(-z2h)));
        }
        if (rlo < Me)
            *(float4*)&g_act[(size_t)(goff + rlo) * H_DIM + n0 + tx * 4] =
                make_float4(olo[0], olo[1], olo[2], olo[3]);
        if (rlo + 1 < Me)
            *(float4*)&g_act[(size_t)(goff + rlo + 1) * H_DIM + n0 + tx * 4] =
                make_float4(ohi[0], ohi[1], ohi[2], ohi[3]);
    }
}

// ---------------- 5) GEMM2: outbuf = act @ wp[e] ----------------
// BM=128 BN=128 BK=16, 256 threads, per-thread 8x8 (m-paired f32x2 accum)
__global__ __launch_bounds__(256) void gemm2_kernel(const float* __restrict__ wp)
{
    const int e = blockIdx.z;
    const int Me = g_counts[e];
    const int m0 = blockIdx.y * 128;
    if (m0 >= Me) return;
    const int n0 = blockIdx.x * 128;
    const int goff = g_offsets[e];
    const float* W = wp + (size_t)e * H_DIM * D_DIM;

    __shared__ __align__(16) float As[16][132];
    __shared__ __align__(16) float Bs[16][132];

    const int tid  = threadIdx.x;
    const int arow = tid >> 1;
    const int akq  = (tid & 1) * 2;
    const float* arp = nullptr;
    if (m0 + arow < Me) arp = g_act + (size_t)(goff + m0 + arow) * H_DIM;

    const int ty = tid >> 4, tx = tid & 15;
    unsigned long long acc[4][8];
#pragma unroll
    for (int i = 0; i < 4; i++)
#pragma unroll
        for (int j = 0; j < 8; j++) acc[i][j] = 0ull;

    for (int kk = 0; kk < H_DIM; kk += 16) {
#pragma unroll
        for (int q = 0; q < 2; q++) {
            int kq = akq + q;
            float4 v = arp ? *(const float4*)(arp + kk + kq * 4)
                           : make_float4(0.f, 0.f, 0.f, 0.f);
            As[kq * 4 + 0][arow] = v.x; As[kq * 4 + 1][arow] = v.y;
            As[kq * 4 + 2][arow] = v.z; As[kq * 4 + 3][arow] = v.w;
        }
#pragma unroll
        for (int q = 0; q < 2; q++) {
            int idx = tid * 2 + q;
            int kr = idx >> 5, c4 = idx & 31;
            *(float4*)&Bs[kr][c4 * 4] =
                *(const float4*)(W + (size_t)(kk + kr) * D_DIM + n0 + c4 * 4);
        }
        __syncthreads();

#pragma unroll
        for (int k = 0; k < 16; k++) {
            ulonglong2 aA = *(ulonglong2*)&As[k][ty * 8];
            ulonglong2 aB = *(ulonglong2*)&As[k][ty * 8 + 4];
            unsigned long long ap[4] = {aA.x, aA.y, aB.x, aB.y};
            float4 bv0 = *(float4*)&Bs[k][tx * 8];
            float4 bv1 = *(float4*)&Bs[k][tx * 8 + 4];
            unsigned long long bb[8] = {pack2(bv0.x), pack2(bv0.y), pack2(bv0.z), pack2(bv0.w),
                                        pack2(bv1.x), pack2(bv1.y), pack2(bv1.z), pack2(bv1.w)};
#pragma unroll
            for (int i = 0; i < 4; i++)
#pragma unroll
                for (int j = 0; j < 8; j++) FMA2(acc[i][j], ap[i], bb[j]);
        }
        __syncthreads();
    }

#pragma unroll
    for (int i = 0; i < 4; i++) {
        int rlo = m0 + ty * 8 + 2 * i;
        float olo[8], ohi[8];
#pragma unroll
        for (int j = 0; j < 8; j++) unpack2(acc[i][j], olo[j], ohi[j]);
        if (rlo < Me) {
            float* dst = &g_outbuf[(size_t)(goff + rlo) * D_DIM + n0 + tx * 8];
            *(float4*)dst       = make_float4(olo[0], olo[1], olo[2], olo[3]);
            *(float4*)(dst + 4) = make_float4(olo[4], olo[5], olo[6], olo[7]);
        }
        if (rlo + 1 < Me) {
            float* dst = &g_outbuf[(size_t)(goff + rlo + 1) * D_DIM + n0 + tx * 8];
            *(float4*)dst       = make_float4(ohi[0], ohi[1], ohi[2], ohi[3]);
            *(float4*)(dst + 4) = make_float4(ohi[4], ohi[5], ohi[6], ohi[7]);
        }
    }
}

// ---------------- 6) combine: y[t] = g0*(o0+bp[e0]) + g1*(o1+bp[e1]) ----------------
__global__ __launch_bounds__(256) void combine_kernel(const float* __restrict__ bp,
                                                      float* __restrict__ y)
{
    int idx = blockIdx.x * 256 + threadIdx.x;
    if (idx >= T_TOK * D_DIM) return;
    int t = idx / D_DIM, d = idx - t * D_DIM;
    int i0 = 2 * t, i1 = 2 * t + 1;
    int r0 = g_inv[i0], r1 = g_inv[i1];
    int e0 = g_topk_id[i0], e1 = g_topk_id[i1];
    float g0 = g_topk_gate[i0], g1 = g_topk_gate[i1];
    float v0 = g_outbuf[(size_t)r0 * D_DIM + d] + bp[e0 * D_DIM + d];
    float v1 = g_outbuf[(size_t)r1 * D_DIM + d] + bp[e1 * D_DIM + d];
    y[idx] = g0 * v0 + g1 * v1;
}

// ---------------- launch ----------------
extern "C" void kernel_launch(void* const* d_in, const int* in_sizes, int n_in,
                              void* d_out, int out_size)
{
    const float* x      = (const float*)d_in[0];
    const float* gate_w = (const float*)d_in[1];
    const float* nw     = (const float*)d_in[2];
    const float* noise  = (const float*)d_in[3];
    const float* w1     = (const float*)d_in[4];
    const float* b1     = (const float*)d_in[5];
    const float* w2     = (const float*)d_in[6];
    const float* b2     = (const float*)d_in[7];
    const float* wp     = (const float*)d_in[8];
    const float* bp     = (const float*)d_in[9];
    float* y = (float*)d_out;
    float* loss_ptr = y + (out_size - 1);

    gate_kernel<<<1024, 256>>>(x, gate_w, nw, noise);
    scan_loss_kernel<<<1, 256>>>(loss_ptr);
    build_kernel<<<64, 256>>>();
    gemm1_kernel<<<dim3(48, 128, 8), 256>>>(x, w1, b1, w2, b2);
    gemm2_kernel<<<dim3(6, 128, 8), 256>>>(wp);
    combine_kernel<<<24576, 256>>>(bp, y);
}